// round 14
// baseline (speedup 1.0000x reference)
#include <cuda_runtime.h>
#include <cuda_fp16.h>
#include <cstdint>
#include <cstddef>

// ---------------- problem dims ----------------
#define B_ROWS 8192
#define K_DIM  4096
#define N_DIM  4096

// ---------------- GEMM tiling -----------------
#define TM 128
#define TN 256
#define KC 64                        // fp16 per k-stage (=128B row, one SW128 atom)
#define NSTAGE 3
#define KSTAGES (K_DIM / KC)         // 64
#define A_TILE_BYTES (TM * KC * 2)   // 16384
#define B_TILE_BYTES (TN * KC * 2)   // 32768
#define STG_BYTES (2 * A_TILE_BYTES + B_TILE_BYTES)   // 65536
#define SMEM_DYN (1024 + NSTAGE * STG_BYTES)          // 197632
#define NTHREADS 256                 // 8 compute warps, 4(m) x 2(n), warp tile 32x128

#define WPREP_BLOCKS N_DIM                                   // 4096
#define PACKX_BLOCKS ((B_ROWS * (K_DIM / 8)) / 256)          // 16384

// ---------------- device scratch ----------------
__device__ __align__(1024) unsigned char g_w_packed[(size_t)N_DIM * K_DIM * 2]; // 32MB
__device__ __align__(1024) unsigned char g_x_hi[(size_t)B_ROWS * K_DIM * 2];    // 64MB
__device__ __align__(1024) unsigned char g_x_lo[(size_t)B_ROWS * K_DIM * 2];    // 64MB
__device__ float g_out[(size_t)B_ROWS * N_DIM];                                  // 128MB row-major
__device__ float g_fc_sf[N_DIM];
__device__ float g_bias_sf[N_DIM];
__device__ float g_b_int[N_DIM];
__device__ unsigned int g_max_bits;

// ---------------- PTX helpers (baseline ISA only, no 'a' features) ----------------
__device__ __forceinline__ uint32_t smem_u32(const void* p) {
    return (uint32_t)__cvta_generic_to_shared(p);
}

#define MBAR_INIT(addr, cnt) \
    asm volatile("mbarrier.init.shared.b64 [%0], %1;" :: "r"(addr), "r"(cnt) : "memory")
#define MBAR_EXPECT_TX(addr, tx) \
    asm volatile("mbarrier.arrive.expect_tx.shared.b64 _, [%0], %1;" :: "r"(addr), "r"(tx) : "memory")

#define MBAR_WAIT(mbar_smem_addr, phase_parity) do { \
    uint32_t _mbar = (uint32_t)(mbar_smem_addr); \
    uint32_t _parity = (uint32_t)(phase_parity); \
    uint32_t _done; \
    asm volatile( \
        "{\n\t.reg .pred p;\n\t" \
        "mbarrier.try_wait.parity.acquire.cta.shared::cta.b64 p, [%1], %2;\n\t" \
        "selp.b32 %0, 1, 0, p;\n\t}" \
        : "=r"(_done) : "r"(_mbar), "r"(_parity) : "memory"); \
    if (!_done) { \
        asm volatile( \
            "{\n\t.reg .pred P1;\n\t" \
            "WAIT_LOOP_%=:\n\t" \
            "mbarrier.try_wait.parity.acquire.cta.shared::cta.b64 P1, [%0], %1, 0x989680;\n\t" \
            "@P1 bra.uni WAIT_DONE_%=;\n\t" \
            "bra.uni WAIT_LOOP_%=;\n\t" \
            "WAIT_DONE_%=:\n\t}" \
            :: "r"(_mbar), "r"(_parity) : "memory"); \
    } \
} while (0)

#define BULK_G2S(dst, src, nbytes, mbar) \
    asm volatile("cp.async.bulk.shared::cluster.global.mbarrier::complete_tx::bytes [%0], [%1], %2, [%3];" \
        :: "r"(dst), "l"(src), "r"(nbytes), "r"(mbar) : "memory")

__device__ __forceinline__ void ldsm_x4(uint32_t (&r)[4], uint32_t addr) {
    asm volatile("ldmatrix.sync.aligned.m8n8.x4.shared.b16 {%0,%1,%2,%3}, [%4];"
                 : "=r"(r[0]), "=r"(r[1]), "=r"(r[2]), "=r"(r[3]) : "r"(addr));
}

// fp32-accumulate HMMA (hi limb)
__device__ __forceinline__ void mma16816(float* c, const uint32_t* a, uint32_t b0, uint32_t b1) {
    asm volatile("mma.sync.aligned.m16n8k16.row.col.f32.f16.f16.f32 "
                 "{%0,%1,%2,%3}, {%4,%5,%6,%7}, {%8,%9}, {%0,%1,%2,%3};"
                 : "+f"(c[0]), "+f"(c[1]), "+f"(c[2]), "+f"(c[3])
                 : "r"(a[0]), "r"(a[1]), "r"(a[2]), "r"(a[3]), "r"(b0), "r"(b1));
}
// fp16-accumulate HMMA (lo limb) — 2 f16x2 accumulator regs
__device__ __forceinline__ void mma16816_h(uint32_t* c, const uint32_t* a, uint32_t b0, uint32_t b1) {
    asm volatile("mma.sync.aligned.m16n8k16.row.col.f16.f16.f16.f16 "
                 "{%0,%1}, {%2,%3,%4,%5}, {%6,%7}, {%0,%1};"
                 : "+r"(c[0]), "+r"(c[1])
                 : "r"(a[0]), "r"(a[1]), "r"(a[2]), "r"(a[3]), "r"(b0), "r"(b1));
}

// =====================================================================
// device helpers for the merged prep kernel
// =====================================================================
__device__ __forceinline__ void do_wprep(int o, int t,
                                         const float* __restrict__ W,
                                         const float* __restrict__ b,
                                         const float* __restrict__ asf,
                                         float* __restrict__ out_fc) {
    __shared__ float red[8];
    __shared__ float fc_sh;
    int lane = t & 31, wrp = t >> 5;

    const float4* w4 = reinterpret_cast<const float4*>(W + (size_t)o * K_DIM) + t * 4;
    float4 v[4];
#pragma unroll
    for (int j = 0; j < 4; j++) v[j] = __ldg(w4 + j);

    float am = 0.f;
#pragma unroll
    for (int j = 0; j < 4; j++)
        am = fmaxf(am, fmaxf(fmaxf(fabsf(v[j].x), fabsf(v[j].y)),
                             fmaxf(fabsf(v[j].z), fabsf(v[j].w))));
#pragma unroll
    for (int off = 16; off > 0; off >>= 1)
        am = fmaxf(am, __shfl_xor_sync(0xFFFFFFFFu, am, off));
    if (lane == 0) red[wrp] = am;
    __syncthreads();
    if (t == 0) {
        float m = red[0];
#pragma unroll
        for (int j = 1; j < 8; j++) m = fmaxf(m, red[j]);
        float fc = __fdiv_rn(fmaxf(m, 1e-8f), 127.0f);
        float a  = __ldg(asf);
        float bs = __fmul_rn(fc, a);
        fc_sh = fc;
        g_fc_sf[o]   = fc;
        g_bias_sf[o] = bs;
        g_b_int[o]   = rintf(__fdiv_rn(__ldg(b + o), bs));
        out_fc[o]    = fc;
        if (o == 0) g_max_bits = 0u;
    }
    __syncthreads();
    float fc = fc_sh;

    // exact division kept: w_int = rint(W/fc) must match reference round-half-even
    float vv[16] = {v[0].x, v[0].y, v[0].z, v[0].w, v[1].x, v[1].y, v[1].z, v[1].w,
                    v[2].x, v[2].y, v[2].z, v[2].w, v[3].x, v[3].y, v[3].z, v[3].w};
    unsigned us[16];
#pragma unroll
    for (int i = 0; i < 16; i++) {
        float r = fminf(fmaxf(rintf(__fdiv_rn(vv[i], fc)), -128.f), 127.f);
        us[i] = (unsigned)__half_as_ushort(__float2half_rn(r));
    }
    int k0 = t * 16;
    int tn = o >> 8, o_in = o & 255, ks = k0 >> 6, k_in = k0 & 63;
    size_t tilebase = ((size_t)(tn * KSTAGES + ks)) << 15;
    unsigned off0 = (unsigned)(o_in * 128 + k_in * 2);
    unsigned off1 = off0 + 16;
    off0 ^= (off0 >> 3) & 0x70;
    off1 ^= (off1 >> 3) & 0x70;
    uint4 p0, p1;
    p0.x = us[0] | (us[1] << 16);  p0.y = us[2] | (us[3] << 16);
    p0.z = us[4] | (us[5] << 16);  p0.w = us[6] | (us[7] << 16);
    p1.x = us[8] | (us[9] << 16);  p1.y = us[10] | (us[11] << 16);
    p1.z = us[12] | (us[13] << 16); p1.w = us[14] | (us[15] << 16);
    *reinterpret_cast<uint4*>(g_w_packed + tilebase + off0) = p0;
    *reinterpret_cast<uint4*>(g_w_packed + tilebase + off1) = p1;
}

__device__ __forceinline__ void do_packx(unsigned g,
                                         const float* __restrict__ X,
                                         const float* __restrict__ asf) {
    int bb = (int)(g >> 9);
    int k  = (int)((g & 511u) << 3);
    float a = __ldg(asf);
    const float4* x4 = reinterpret_cast<const float4*>(X + (size_t)bb * K_DIM + k);
    float4 v0 = __ldg(x4), v1 = __ldg(x4 + 1);
    float vv[8] = {v0.x, v0.y, v0.z, v0.w, v1.x, v1.y, v1.z, v1.w};
    unsigned uh[8], ul[8];
#pragma unroll
    for (int i = 0; i < 8; i++) {
        float xi = __fdiv_rn(vv[i], a);
        __half hh = __float2half_rn(xi);
        float lo = xi - __half2float(hh);   // exact
        uh[i] = (unsigned)__half_as_ushort(hh);
        ul[i] = (unsigned)__half_as_ushort(__float2half_rn(lo));
    }
    uint4 ph, pl;
    ph.x = uh[0] | (uh[1] << 16); ph.y = uh[2] | (uh[3] << 16);
    ph.z = uh[4] | (uh[5] << 16); ph.w = uh[6] | (uh[7] << 16);
    pl.x = ul[0] | (ul[1] << 16); pl.y = ul[2] | (ul[3] << 16);
    pl.z = ul[4] | (ul[5] << 16); pl.w = ul[6] | (ul[7] << 16);
    int tm = bb >> 7, m_in = bb & 127, ks = k >> 6, k_in = k & 63;
    unsigned off = (unsigned)(m_in * 128 + k_in * 2);
    off ^= (off >> 3) & 0x70;
    size_t tb = ((size_t)(tm * KSTAGES + ks)) << 14;
    *reinterpret_cast<uint4*>(g_x_hi + tb + off) = ph;
    *reinterpret_cast<uint4*>(g_x_lo + tb + off) = pl;
}

// =====================================================================
// K1: merged prep — streaming packx blocks FIRST (fill DRAM early),
//     sync-heavy wprep blocks last (overlap the streaming tail).
// =====================================================================
__global__ void __launch_bounds__(256) k_prep(const float* __restrict__ W,
                                              const float* __restrict__ b,
                                              const float* __restrict__ asf,
                                              const float* __restrict__ X,
                                              float* __restrict__ out_fc) {
    int bid = blockIdx.x;
    if (bid < PACKX_BLOCKS) {
        unsigned g = (unsigned)bid * 256u + threadIdx.x;
        do_packx(g, X, asf);
    } else {
        do_wprep(bid - PACKX_BLOCKS, threadIdx.x, W, b, asf, out_fc);
    }
}

// =====================================================================
// K2: lockstep mma.sync GEMM, 128x256 CTA tile, 8 warps (32x128 warp tile).
//     hi limb -> HMMA fp32-acc; lo limb -> HMMA fp16-acc.
//     Tensor-issue saturated (r32~14.2, r16~3.7 cyc/SMSP measured).
// =====================================================================
__global__ void __launch_bounds__(NTHREADS, 1) k_gemm() {
    extern __shared__ unsigned char smem_raw[];
    __shared__ __align__(8) uint64_t full_bar[NSTAGE];
    uint32_t base = (smem_u32(smem_raw) + 1023u) & ~1023u;
    uint32_t fb0 = smem_u32(full_bar);

    int tid = threadIdx.x;
    int lane = tid & 31;
    int w = tid >> 5;
    int wm = w & 3;        // 4 warps along M (32 rows each)
    int wn = w >> 2;       // 2 warps along N (128 cols each)
    int bid = blockIdx.x;
    int tn = bid & 15;
    int tm = bid >> 4;

    if (tid == 0) {
#pragma unroll
        for (int s = 0; s < NSTAGE; s++) MBAR_INIT(fb0 + s * 8, 1);
    }
    __syncthreads();

    const unsigned char* sAh = g_x_hi + (size_t)(tm * KSTAGES) * A_TILE_BYTES;
    const unsigned char* sAl = g_x_lo + (size_t)(tm * KSTAGES) * A_TILE_BYTES;
    const unsigned char* sB  = g_w_packed + (size_t)(tn * KSTAGES) * B_TILE_BYTES;

    if (tid == 0) {
#pragma unroll
        for (int s = 0; s < NSTAGE; s++) {
            uint32_t st = base + s * STG_BYTES;
            uint32_t fb = fb0 + s * 8;
            MBAR_EXPECT_TX(fb, STG_BYTES);
            BULK_G2S(st,                    sAh + (size_t)s * A_TILE_BYTES, A_TILE_BYTES, fb);
            BULK_G2S(st + A_TILE_BYTES,     sAl + (size_t)s * A_TILE_BYTES, A_TILE_BYTES, fb);
            BULK_G2S(st + 2 * A_TILE_BYTES, sB  + (size_t)s * B_TILE_BYTES, B_TILE_BYTES, fb);
        }
    }

    int arow = lane & 15;
    int agr16 = (lane >> 4) << 4;

    uint32_t aoff[2];
#pragma unroll
    for (int mf = 0; mf < 2; mf++) {
        uint32_t r = (uint32_t)((wm * 32 + mf * 16 + arow) * 128 + agr16);
        aoff[mf] = r ^ ((r >> 3) & 0x70);
    }
    uint32_t boff[8];
#pragma unroll
    for (int np = 0; np < 8; np++) {
        uint32_t r = (uint32_t)((wn * 128 + np * 16 + arow) * 128 + agr16);
        boff[np] = (r ^ ((r >> 3) & 0x70)) + 2 * A_TILE_BYTES;
    }

    float    acch[2][16][4];   // hi limb, fp32
    uint32_t accl[2][16][2];   // lo limb, fp16x2 pairs
#pragma unroll
    for (int i = 0; i < 2; i++)
#pragma unroll
        for (int j = 0; j < 16; j++) {
#pragma unroll
            for (int r = 0; r < 4; r++) acch[i][j][r] = 0.f;
            accl[i][j][0] = 0u; accl[i][j][1] = 0u;
        }

    for (int ksi = 0; ksi < KSTAGES; ksi++) {
        int s = ksi % NSTAGE;
        int par = (ksi / NSTAGE) & 1;
        MBAR_WAIT(fb0 + s * 8, par);
        uint32_t st = base + s * STG_BYTES;
#pragma unroll
        for (int kk = 0; kk < 4; kk++) {
            uint32_t kx = (uint32_t)(kk << 5);
            uint32_t afr[2][2][4];   // [limb][mf][4]
#pragma unroll
            for (int mf = 0; mf < 2; mf++) {
                uint32_t a0 = st + (aoff[mf] ^ kx);
                ldsm_x4(afr[0][mf], a0);
                ldsm_x4(afr[1][mf], a0 + A_TILE_BYTES);
            }
#pragma unroll
            for (int np = 0; np < 8; np++) {
                uint32_t bfr[4];
                ldsm_x4(bfr, st + (boff[np] ^ kx));
#pragma unroll
                for (int mf = 0; mf < 2; mf++) {
                    mma16816(acch[mf][2 * np],     afr[0][mf], bfr[0], bfr[2]);
                    mma16816(acch[mf][2 * np + 1], afr[0][mf], bfr[1], bfr[3]);
                    mma16816_h(accl[mf][2 * np],     afr[1][mf], bfr[0], bfr[2]);
                    mma16816_h(accl[mf][2 * np + 1], afr[1][mf], bfr[1], bfr[3]);
                }
            }
        }
        __syncthreads();
        if (ksi + NSTAGE < KSTAGES && tid == 0) {
            int ns = ksi + NSTAGE;
            uint32_t st2 = base + s * STG_BYTES;
            uint32_t fb = fb0 + s * 8;
            MBAR_EXPECT_TX(fb, STG_BYTES);
            BULK_G2S(st2,                    sAh + (size_t)ns * A_TILE_BYTES, A_TILE_BYTES, fb);
            BULK_G2S(st2 + A_TILE_BYTES,     sAl + (size_t)ns * A_TILE_BYTES, A_TILE_BYTES, fb);
            BULK_G2S(st2 + 2 * A_TILE_BYTES, sB  + (size_t)ns * B_TILE_BYTES, B_TILE_BYTES, fb);
        }
    }

    // -------- epilogue: out = (hi + lo + b_int)*bias_sf, ReLU, max --------
    float lmax = 0.f;
    int orow = lane >> 2;
    int ocol = (lane & 3) * 2;
    int obase = tn * TN + wn * 128;
    size_t mbase = (size_t)tm * TM + wm * 32 + orow;
#pragma unroll
    for (int mf = 0; mf < 2; mf++) {
        size_t m0 = mbase + mf * 16;
#pragma unroll
        for (int nf = 0; nf < 16; nf++) {
            int o = obase + nf * 8 + ocol;
            float bs0 = __ldg(&g_bias_sf[o]);
            float bs1 = __ldg(&g_bias_sf[o + 1]);
            float bi0 = __ldg(&g_b_int[o]);
            float bi1 = __ldg(&g_b_int[o + 1]);
            float2 lo0 = __half22float2(*reinterpret_cast<const __half2*>(&accl[mf][nf][0]));
            float2 lo1 = __half22float2(*reinterpret_cast<const __half2*>(&accl[mf][nf][1]));
            float v0 = fmaxf((acch[mf][nf][0] + lo0.x + bi0) * bs0, 0.f);
            float v1 = fmaxf((acch[mf][nf][1] + lo0.y + bi1) * bs1, 0.f);
            float v2 = fmaxf((acch[mf][nf][2] + lo1.x + bi0) * bs0, 0.f);
            float v3 = fmaxf((acch[mf][nf][3] + lo1.y + bi1) * bs1, 0.f);
            lmax = fmaxf(lmax, fmaxf(fmaxf(v0, v1), fmaxf(v2, v3)));
            *reinterpret_cast<float2*>(&g_out[m0 * N_DIM + o]) = make_float2(v0, v1);
            *reinterpret_cast<float2*>(&g_out[(m0 + 8) * N_DIM + o]) = make_float2(v2, v3);
        }
    }
#pragma unroll
    for (int off = 16; off > 0; off >>= 1)
        lmax = fmaxf(lmax, __shfl_xor_sync(0xFFFFFFFFu, lmax, off));
    if (lane == 0) atomicMax(&g_max_bits, __float_as_uint(lmax));
}

// =====================================================================
// K3: requantize (sf computed in-kernel from g_max_bits; zp = 0).
//     8 floats per thread (two contiguous float4s).
// =====================================================================
__global__ void __launch_bounds__(256) k_requant(float* __restrict__ out,
                                                 float* __restrict__ out_tail) {
    float xm = __uint_as_float(g_max_bits);
    float sf = __fdiv_rn(fmaxf(xm, 1e-8f), 255.0f);
    if (blockIdx.x == 0 && threadIdx.x == 0) out_tail[0] = sf;
    size_t i = ((size_t)blockIdx.x * 256 + threadIdx.x) * 8;
    float4 v0 = *reinterpret_cast<const float4*>(&g_out[i]);
    float4 v1 = *reinterpret_cast<const float4*>(&g_out[i + 4]);
    float4 r0, r1;
    r0.x = fminf(fmaxf(rintf(__fdiv_rn(v0.x, sf)), 0.f), 255.f) * sf;
    r0.y = fminf(fmaxf(rintf(__fdiv_rn(v0.y, sf)), 0.f), 255.f) * sf;
    r0.z = fminf(fmaxf(rintf(__fdiv_rn(v0.z, sf)), 0.f), 255.f) * sf;
    r0.w = fminf(fmaxf(rintf(__fdiv_rn(v0.w, sf)), 0.f), 255.f) * sf;
    r1.x = fminf(fmaxf(rintf(__fdiv_rn(v1.x, sf)), 0.f), 255.f) * sf;
    r1.y = fminf(fmaxf(rintf(__fdiv_rn(v1.y, sf)), 0.f), 255.f) * sf;
    r1.z = fminf(fmaxf(rintf(__fdiv_rn(v1.z, sf)), 0.f), 255.f) * sf;
    r1.w = fminf(fmaxf(rintf(__fdiv_rn(v1.w, sf)), 0.f), 255.f) * sf;
    *reinterpret_cast<float4*>(&out[i]) = r0;
    *reinterpret_cast<float4*>(&out[i + 4]) = r1;
}

// =====================================================================
// launch
// =====================================================================
extern "C" void kernel_launch(void* const* d_in, const int* in_sizes, int n_in,
                              void* d_out, int out_size) {
    const float* x = nullptr;
    const float* asf = nullptr;
    const float* W = nullptr;
    const float* b = nullptr;
    for (int i = 0; i < n_in; i++) {
        long s = in_sizes[i];
        if (s == (long)B_ROWS * K_DIM)      x   = (const float*)d_in[i];
        else if (s == (long)N_DIM * K_DIM)  W   = (const float*)d_in[i];
        else if (s == N_DIM)                b   = (const float*)d_in[i];
        else if (s == 1)                    asf = (const float*)d_in[i];
    }
    if (!x)   x   = (const float*)d_in[0];
    if (!asf) asf = (const float*)d_in[1];
    if (!W)   W   = (const float*)d_in[2];
    if (!b)   b   = (const float*)d_in[3];

    float* out = (float*)d_out;
    float* out_fc   = out + (size_t)B_ROWS * N_DIM;
    float* out_tail = out_fc + N_DIM;

    cudaFuncSetAttribute(k_gemm, cudaFuncAttributeMaxDynamicSharedMemorySize, SMEM_DYN);

    k_prep<<<WPREP_BLOCKS + PACKX_BLOCKS, 256>>>(W, b, asf, x, out_fc);
    k_gemm<<<(B_ROWS / TM) * (N_DIM / TN), NTHREADS, SMEM_DYN>>>();
    k_requant<<<(B_ROWS * N_DIM) / (256 * 8), 256>>>(out, out_tail);
}

// round 15
// speedup vs baseline: 1.0044x; 1.0044x over previous
#include <cuda_runtime.h>
#include <cuda_fp16.h>
#include <cstdint>
#include <cstddef>

// ---------------- problem dims ----------------
#define B_ROWS 8192
#define K_DIM  4096
#define N_DIM  4096

// ---------------- GEMM tiling -----------------
#define TM 128
#define TN 256
#define KC 64                        // fp16 per k-stage (=128B row, one SW128 atom)
#define NSTAGE 3
#define KSTAGES (K_DIM / KC)         // 64
#define A_TILE_BYTES (TM * KC * 2)   // 16384
#define B_TILE_BYTES (TN * KC * 2)   // 32768
#define STG_BYTES (2 * A_TILE_BYTES + B_TILE_BYTES)   // 65536
#define SMEM_DYN (1024 + NSTAGE * STG_BYTES)          // 197632
#define NTHREADS 256                 // 8 compute warps, 4(m) x 2(n), warp tile 32x128

#define WPREP_BLOCKS N_DIM                                   // 4096
#define PACKX_BLOCKS ((B_ROWS * (K_DIM / 8)) / 256)          // 16384

// ---------------- device scratch ----------------
__device__ __align__(1024) unsigned char g_w_packed[(size_t)N_DIM * K_DIM * 2]; // 32MB
__device__ __align__(1024) unsigned char g_x_hi[(size_t)B_ROWS * K_DIM * 2];    // 64MB
__device__ __align__(1024) unsigned char g_x_lo[(size_t)B_ROWS * K_DIM * 2];    // 64MB
__device__ float g_out[(size_t)B_ROWS * N_DIM];                                  // 128MB row-major
__device__ float g_fc_sf[N_DIM];
__device__ float g_bias_sf[N_DIM];
__device__ float g_b_int[N_DIM];
__device__ unsigned int g_max_bits;

// ---------------- PTX helpers (baseline ISA only, no 'a' features) ----------------
__device__ __forceinline__ uint32_t smem_u32(const void* p) {
    return (uint32_t)__cvta_generic_to_shared(p);
}

#define MBAR_INIT(addr, cnt) \
    asm volatile("mbarrier.init.shared.b64 [%0], %1;" :: "r"(addr), "r"(cnt) : "memory")
#define MBAR_EXPECT_TX(addr, tx) \
    asm volatile("mbarrier.arrive.expect_tx.shared.b64 _, [%0], %1;" :: "r"(addr), "r"(tx) : "memory")

#define MBAR_WAIT(mbar_smem_addr, phase_parity) do { \
    uint32_t _mbar = (uint32_t)(mbar_smem_addr); \
    uint32_t _parity = (uint32_t)(phase_parity); \
    uint32_t _done; \
    asm volatile( \
        "{\n\t.reg .pred p;\n\t" \
        "mbarrier.try_wait.parity.acquire.cta.shared::cta.b64 p, [%1], %2;\n\t" \
        "selp.b32 %0, 1, 0, p;\n\t}" \
        : "=r"(_done) : "r"(_mbar), "r"(_parity) : "memory"); \
    if (!_done) { \
        asm volatile( \
            "{\n\t.reg .pred P1;\n\t" \
            "WAIT_LOOP_%=:\n\t" \
            "mbarrier.try_wait.parity.acquire.cta.shared::cta.b64 P1, [%0], %1, 0x989680;\n\t" \
            "@P1 bra.uni WAIT_DONE_%=;\n\t" \
            "bra.uni WAIT_LOOP_%=;\n\t" \
            "WAIT_DONE_%=:\n\t}" \
            :: "r"(_mbar), "r"(_parity) : "memory"); \
    } \
} while (0)

#define BULK_G2S(dst, src, nbytes, mbar) \
    asm volatile("cp.async.bulk.shared::cluster.global.mbarrier::complete_tx::bytes [%0], [%1], %2, [%3];" \
        :: "r"(dst), "l"(src), "r"(nbytes), "r"(mbar) : "memory")

__device__ __forceinline__ void ldsm_x4(uint32_t (&r)[4], uint32_t addr) {
    asm volatile("ldmatrix.sync.aligned.m8n8.x4.shared.b16 {%0,%1,%2,%3}, [%4];"
                 : "=r"(r[0]), "=r"(r[1]), "=r"(r[2]), "=r"(r[3]) : "r"(addr));
}

// fp32-accumulate HMMA (hi limb)
__device__ __forceinline__ void mma16816(float* c, const uint32_t* a, uint32_t b0, uint32_t b1) {
    asm volatile("mma.sync.aligned.m16n8k16.row.col.f32.f16.f16.f32 "
                 "{%0,%1,%2,%3}, {%4,%5,%6,%7}, {%8,%9}, {%0,%1,%2,%3};"
                 : "+f"(c[0]), "+f"(c[1]), "+f"(c[2]), "+f"(c[3])
                 : "r"(a[0]), "r"(a[1]), "r"(a[2]), "r"(a[3]), "r"(b0), "r"(b1));
}
// fp16-accumulate HMMA (lo limb) — 2 f16x2 accumulator regs
__device__ __forceinline__ void mma16816_h(uint32_t* c, const uint32_t* a, uint32_t b0, uint32_t b1) {
    asm volatile("mma.sync.aligned.m16n8k16.row.col.f16.f16.f16.f16 "
                 "{%0,%1}, {%2,%3,%4,%5}, {%6,%7}, {%0,%1};"
                 : "+r"(c[0]), "+r"(c[1])
                 : "r"(a[0]), "r"(a[1]), "r"(a[2]), "r"(a[3]), "r"(b0), "r"(b1));
}

// =====================================================================
// device helpers for the merged prep kernel
// =====================================================================
__device__ __forceinline__ void do_wprep(int o, int t,
                                         const float* __restrict__ W,
                                         const float* __restrict__ b,
                                         const float* __restrict__ asf,
                                         float* __restrict__ out_fc) {
    __shared__ float red[8];
    __shared__ float fc_sh;
    int lane = t & 31, wrp = t >> 5;

    const float4* w4 = reinterpret_cast<const float4*>(W + (size_t)o * K_DIM) + t * 4;
    float4 v[4];
#pragma unroll
    for (int j = 0; j < 4; j++) v[j] = __ldg(w4 + j);

    float am = 0.f;
#pragma unroll
    for (int j = 0; j < 4; j++)
        am = fmaxf(am, fmaxf(fmaxf(fabsf(v[j].x), fabsf(v[j].y)),
                             fmaxf(fabsf(v[j].z), fabsf(v[j].w))));
#pragma unroll
    for (int off = 16; off > 0; off >>= 1)
        am = fmaxf(am, __shfl_xor_sync(0xFFFFFFFFu, am, off));
    if (lane == 0) red[wrp] = am;
    __syncthreads();
    if (t == 0) {
        float m = red[0];
#pragma unroll
        for (int j = 1; j < 8; j++) m = fmaxf(m, red[j]);
        float fc = __fdiv_rn(fmaxf(m, 1e-8f), 127.0f);
        float a  = __ldg(asf);
        float bs = __fmul_rn(fc, a);
        fc_sh = fc;
        g_fc_sf[o]   = fc;
        g_bias_sf[o] = bs;
        g_b_int[o]   = rintf(__fdiv_rn(__ldg(b + o), bs));
        out_fc[o]    = fc;
        if (o == 0) g_max_bits = 0u;
    }
    __syncthreads();
    float fc = fc_sh;

    // exact division kept: w_int = rint(W/fc) must match reference round-half-even
    float vv[16] = {v[0].x, v[0].y, v[0].z, v[0].w, v[1].x, v[1].y, v[1].z, v[1].w,
                    v[2].x, v[2].y, v[2].z, v[2].w, v[3].x, v[3].y, v[3].z, v[3].w};
    unsigned us[16];
#pragma unroll
    for (int i = 0; i < 16; i++) {
        float r = fminf(fmaxf(rintf(__fdiv_rn(vv[i], fc)), -128.f), 127.f);
        us[i] = (unsigned)__half_as_ushort(__float2half_rn(r));
    }
    int k0 = t * 16;
    int tn = o >> 8, o_in = o & 255, ks = k0 >> 6, k_in = k0 & 63;
    size_t tilebase = ((size_t)(tn * KSTAGES + ks)) << 15;
    unsigned off0 = (unsigned)(o_in * 128 + k_in * 2);
    unsigned off1 = off0 + 16;
    off0 ^= (off0 >> 3) & 0x70;
    off1 ^= (off1 >> 3) & 0x70;
    uint4 p0, p1;
    p0.x = us[0] | (us[1] << 16);  p0.y = us[2] | (us[3] << 16);
    p0.z = us[4] | (us[5] << 16);  p0.w = us[6] | (us[7] << 16);
    p1.x = us[8] | (us[9] << 16);  p1.y = us[10] | (us[11] << 16);
    p1.z = us[12] | (us[13] << 16); p1.w = us[14] | (us[15] << 16);
    *reinterpret_cast<uint4*>(g_w_packed + tilebase + off0) = p0;
    *reinterpret_cast<uint4*>(g_w_packed + tilebase + off1) = p1;
}

__device__ __forceinline__ void do_packx(unsigned g,
                                         const float* __restrict__ X,
                                         const float* __restrict__ asf) {
    int bb = (int)(g >> 9);
    int k  = (int)((g & 511u) << 3);
    float a = __ldg(asf);
    const float4* x4 = reinterpret_cast<const float4*>(X + (size_t)bb * K_DIM + k);
    float4 v0 = __ldg(x4), v1 = __ldg(x4 + 1);
    float vv[8] = {v0.x, v0.y, v0.z, v0.w, v1.x, v1.y, v1.z, v1.w};
    unsigned uh[8], ul[8];
#pragma unroll
    for (int i = 0; i < 8; i++) {
        float xi = __fdiv_rn(vv[i], a);
        __half hh = __float2half_rn(xi);
        float lo = xi - __half2float(hh);   // exact
        uh[i] = (unsigned)__half_as_ushort(hh);
        ul[i] = (unsigned)__half_as_ushort(__float2half_rn(lo));
    }
    uint4 ph, pl;
    ph.x = uh[0] | (uh[1] << 16); ph.y = uh[2] | (uh[3] << 16);
    ph.z = uh[4] | (uh[5] << 16); ph.w = uh[6] | (uh[7] << 16);
    pl.x = ul[0] | (ul[1] << 16); pl.y = ul[2] | (ul[3] << 16);
    pl.z = ul[4] | (ul[5] << 16); pl.w = ul[6] | (ul[7] << 16);
    int tm = bb >> 7, m_in = bb & 127, ks = k >> 6, k_in = k & 63;
    unsigned off = (unsigned)(m_in * 128 + k_in * 2);
    off ^= (off >> 3) & 0x70;
    size_t tb = ((size_t)(tm * KSTAGES + ks)) << 14;
    *reinterpret_cast<uint4*>(g_x_hi + tb + off) = ph;
    *reinterpret_cast<uint4*>(g_x_lo + tb + off) = pl;
}

// =====================================================================
// K1: merged prep — blocks [0,4096) do W prep; rest do X pack.
//     (round-12 branch order: measured 32 regs / 83% occ / 55.5us)
// =====================================================================
__global__ void __launch_bounds__(256) k_prep(const float* __restrict__ W,
                                              const float* __restrict__ b,
                                              const float* __restrict__ asf,
                                              const float* __restrict__ X,
                                              float* __restrict__ out_fc) {
    int bid = blockIdx.x;
    if (bid < WPREP_BLOCKS) {
        do_wprep(bid, threadIdx.x, W, b, asf, out_fc);
    } else {
        unsigned g = (unsigned)(bid - WPREP_BLOCKS) * 256u + threadIdx.x;
        do_packx(g, X, asf);
    }
}

// =====================================================================
// K2: lockstep mma.sync GEMM, 128x256 CTA tile, 8 warps (32x128 warp tile).
//     hi limb -> HMMA fp32-acc; lo limb -> HMMA fp16-acc.
//     Tensor-issue saturated (r32~14.2, r16~3.7 cyc/SMSP measured).
// =====================================================================
__global__ void __launch_bounds__(NTHREADS, 1) k_gemm() {
    extern __shared__ unsigned char smem_raw[];
    __shared__ __align__(8) uint64_t full_bar[NSTAGE];
    uint32_t base = (smem_u32(smem_raw) + 1023u) & ~1023u;
    uint32_t fb0 = smem_u32(full_bar);

    int tid = threadIdx.x;
    int lane = tid & 31;
    int w = tid >> 5;
    int wm = w & 3;        // 4 warps along M (32 rows each)
    int wn = w >> 2;       // 2 warps along N (128 cols each)
    int bid = blockIdx.x;
    int tn = bid & 15;
    int tm = bid >> 4;

    if (tid == 0) {
#pragma unroll
        for (int s = 0; s < NSTAGE; s++) MBAR_INIT(fb0 + s * 8, 1);
    }
    __syncthreads();

    const unsigned char* sAh = g_x_hi + (size_t)(tm * KSTAGES) * A_TILE_BYTES;
    const unsigned char* sAl = g_x_lo + (size_t)(tm * KSTAGES) * A_TILE_BYTES;
    const unsigned char* sB  = g_w_packed + (size_t)(tn * KSTAGES) * B_TILE_BYTES;

    if (tid == 0) {
#pragma unroll
        for (int s = 0; s < NSTAGE; s++) {
            uint32_t st = base + s * STG_BYTES;
            uint32_t fb = fb0 + s * 8;
            MBAR_EXPECT_TX(fb, STG_BYTES);
            BULK_G2S(st,                    sAh + (size_t)s * A_TILE_BYTES, A_TILE_BYTES, fb);
            BULK_G2S(st + A_TILE_BYTES,     sAl + (size_t)s * A_TILE_BYTES, A_TILE_BYTES, fb);
            BULK_G2S(st + 2 * A_TILE_BYTES, sB  + (size_t)s * B_TILE_BYTES, B_TILE_BYTES, fb);
        }
    }

    int arow = lane & 15;
    int agr16 = (lane >> 4) << 4;

    uint32_t aoff[2];
#pragma unroll
    for (int mf = 0; mf < 2; mf++) {
        uint32_t r = (uint32_t)((wm * 32 + mf * 16 + arow) * 128 + agr16);
        aoff[mf] = r ^ ((r >> 3) & 0x70);
    }
    uint32_t boff[8];
#pragma unroll
    for (int np = 0; np < 8; np++) {
        uint32_t r = (uint32_t)((wn * 128 + np * 16 + arow) * 128 + agr16);
        boff[np] = (r ^ ((r >> 3) & 0x70)) + 2 * A_TILE_BYTES;
    }

    float    acch[2][16][4];   // hi limb, fp32
    uint32_t accl[2][16][2];   // lo limb, fp16x2 pairs
#pragma unroll
    for (int i = 0; i < 2; i++)
#pragma unroll
        for (int j = 0; j < 16; j++) {
#pragma unroll
            for (int r = 0; r < 4; r++) acch[i][j][r] = 0.f;
            accl[i][j][0] = 0u; accl[i][j][1] = 0u;
        }

    for (int ksi = 0; ksi < KSTAGES; ksi++) {
        int s = ksi % NSTAGE;
        int par = (ksi / NSTAGE) & 1;
        MBAR_WAIT(fb0 + s * 8, par);
        uint32_t st = base + s * STG_BYTES;
#pragma unroll
        for (int kk = 0; kk < 4; kk++) {
            uint32_t kx = (uint32_t)(kk << 5);
            uint32_t afr[2][2][4];   // [limb][mf][4]
#pragma unroll
            for (int mf = 0; mf < 2; mf++) {
                uint32_t a0 = st + (aoff[mf] ^ kx);
                ldsm_x4(afr[0][mf], a0);
                ldsm_x4(afr[1][mf], a0 + A_TILE_BYTES);
            }
#pragma unroll
            for (int np = 0; np < 8; np++) {
                uint32_t bfr[4];
                ldsm_x4(bfr, st + (boff[np] ^ kx));
#pragma unroll
                for (int mf = 0; mf < 2; mf++) {
                    mma16816(acch[mf][2 * np],     afr[0][mf], bfr[0], bfr[2]);
                    mma16816(acch[mf][2 * np + 1], afr[0][mf], bfr[1], bfr[3]);
                    mma16816_h(accl[mf][2 * np],     afr[1][mf], bfr[0], bfr[2]);
                    mma16816_h(accl[mf][2 * np + 1], afr[1][mf], bfr[1], bfr[3]);
                }
            }
        }
        __syncthreads();
        if (ksi + NSTAGE < KSTAGES && tid == 0) {
            int ns = ksi + NSTAGE;
            uint32_t st2 = base + s * STG_BYTES;
            uint32_t fb = fb0 + s * 8;
            MBAR_EXPECT_TX(fb, STG_BYTES);
            BULK_G2S(st2,                    sAh + (size_t)ns * A_TILE_BYTES, A_TILE_BYTES, fb);
            BULK_G2S(st2 + A_TILE_BYTES,     sAl + (size_t)ns * A_TILE_BYTES, A_TILE_BYTES, fb);
            BULK_G2S(st2 + 2 * A_TILE_BYTES, sB  + (size_t)ns * B_TILE_BYTES, B_TILE_BYTES, fb);
        }
    }

    // -------- epilogue: out = (hi + lo + b_int)*bias_sf, ReLU, max --------
    float lmax = 0.f;
    int orow = lane >> 2;
    int ocol = (lane & 3) * 2;
    int obase = tn * TN + wn * 128;
    size_t mbase = (size_t)tm * TM + wm * 32 + orow;
#pragma unroll
    for (int mf = 0; mf < 2; mf++) {
        size_t m0 = mbase + mf * 16;
#pragma unroll
        for (int nf = 0; nf < 16; nf++) {
            int o = obase + nf * 8 + ocol;
            float bs0 = __ldg(&g_bias_sf[o]);
            float bs1 = __ldg(&g_bias_sf[o + 1]);
            float bi0 = __ldg(&g_b_int[o]);
            float bi1 = __ldg(&g_b_int[o + 1]);
            float2 lo0 = __half22float2(*reinterpret_cast<const __half2*>(&accl[mf][nf][0]));
            float2 lo1 = __half22float2(*reinterpret_cast<const __half2*>(&accl[mf][nf][1]));
            float v0 = fmaxf((acch[mf][nf][0] + lo0.x + bi0) * bs0, 0.f);
            float v1 = fmaxf((acch[mf][nf][1] + lo0.y + bi1) * bs1, 0.f);
            float v2 = fmaxf((acch[mf][nf][2] + lo1.x + bi0) * bs0, 0.f);
            float v3 = fmaxf((acch[mf][nf][3] + lo1.y + bi1) * bs1, 0.f);
            lmax = fmaxf(lmax, fmaxf(fmaxf(v0, v1), fmaxf(v2, v3)));
            *reinterpret_cast<float2*>(&g_out[m0 * N_DIM + o]) = make_float2(v0, v1);
            *reinterpret_cast<float2*>(&g_out[(m0 + 8) * N_DIM + o]) = make_float2(v2, v3);
        }
    }
#pragma unroll
    for (int off = 16; off > 0; off >>= 1)
        lmax = fmaxf(lmax, __shfl_xor_sync(0xFFFFFFFFu, lmax, off));
    if (lane == 0) atomicMax(&g_max_bits, __float_as_uint(lmax));
}

// =====================================================================
// K3: requantize (sf computed in-kernel from g_max_bits; zp = 0).
//     8 floats per thread (two contiguous float4s) — measured win.
// =====================================================================
__global__ void __launch_bounds__(256) k_requant(float* __restrict__ out,
                                                 float* __restrict__ out_tail) {
    float xm = __uint_as_float(g_max_bits);
    float sf = __fdiv_rn(fmaxf(xm, 1e-8f), 255.0f);
    if (blockIdx.x == 0 && threadIdx.x == 0) out_tail[0] = sf;
    size_t i = ((size_t)blockIdx.x * 256 + threadIdx.x) * 8;
    float4 v0 = *reinterpret_cast<const float4*>(&g_out[i]);
    float4 v1 = *reinterpret_cast<const float4*>(&g_out[i + 4]);
    float4 r0, r1;
    r0.x = fminf(fmaxf(rintf(__fdiv_rn(v0.x, sf)), 0.f), 255.f) * sf;
    r0.y = fminf(fmaxf(rintf(__fdiv_rn(v0.y, sf)), 0.f), 255.f) * sf;
    r0.z = fminf(fmaxf(rintf(__fdiv_rn(v0.z, sf)), 0.f), 255.f) * sf;
    r0.w = fminf(fmaxf(rintf(__fdiv_rn(v0.w, sf)), 0.f), 255.f) * sf;
    r1.x = fminf(fmaxf(rintf(__fdiv_rn(v1.x, sf)), 0.f), 255.f) * sf;
    r1.y = fminf(fmaxf(rintf(__fdiv_rn(v1.y, sf)), 0.f), 255.f) * sf;
    r1.z = fminf(fmaxf(rintf(__fdiv_rn(v1.z, sf)), 0.f), 255.f) * sf;
    r1.w = fminf(fmaxf(rintf(__fdiv_rn(v1.w, sf)), 0.f), 255.f) * sf;
    *reinterpret_cast<float4*>(&out[i]) = r0;
    *reinterpret_cast<float4*>(&out[i + 4]) = r1;
}

// =====================================================================
// launch
// =====================================================================
extern "C" void kernel_launch(void* const* d_in, const int* in_sizes, int n_in,
                              void* d_out, int out_size) {
    const float* x = nullptr;
    const float* asf = nullptr;
    const float* W = nullptr;
    const float* b = nullptr;
    for (int i = 0; i < n_in; i++) {
        long s = in_sizes[i];
        if (s == (long)B_ROWS * K_DIM)      x   = (const float*)d_in[i];
        else if (s == (long)N_DIM * K_DIM)  W   = (const float*)d_in[i];
        else if (s == N_DIM)                b   = (const float*)d_in[i];
        else if (s == 1)                    asf = (const float*)d_in[i];
    }
    if (!x)   x   = (const float*)d_in[0];
    if (!asf) asf = (const float*)d_in[1];
    if (!W)   W   = (const float*)d_in[2];
    if (!b)   b   = (const float*)d_in[3];

    float* out = (float*)d_out;
    float* out_fc   = out + (size_t)B_ROWS * N_DIM;
    float* out_tail = out_fc + N_DIM;

    cudaFuncSetAttribute(k_gemm, cudaFuncAttributeMaxDynamicSharedMemorySize, SMEM_DYN);

    k_prep<<<WPREP_BLOCKS + PACKX_BLOCKS, 256>>>(W, b, asf, x, out_fc);
    k_gemm<<<(B_ROWS / TM) * (N_DIM / TN), NTHREADS, SMEM_DYN>>>();
    k_requant<<<(B_ROWS * N_DIM) / (256 * 8), 256>>>(out, out_tail);
}